// round 1
// baseline (speedup 1.0000x reference)
#include <cuda_runtime.h>
#include <math.h>

// Problem constants
#define BB   4
#define SS   2048
#define DD   256
#define HH   8
#define LL   4
#define FFD  512
#define DK   32
#define NTOK (BB*SS)        // 8192
#define SCALE 0.17677669529663687f  // 1/sqrt(32)

// -------- device scratch (no allocations allowed) --------
__device__ float g_x [NTOK*DD];   // residual stream h
__device__ float g_x2[NTOK*DD];   // LN output
__device__ float g_q [NTOK*DD];
__device__ float g_k [NTOK*DD];
__device__ float g_v [NTOK*DD];
__device__ float g_o [NTOK*DD];
__device__ float g_ff[NTOK*FFD];

// ============================================================
// LayerNorm: one block per token, 256 threads (= D)
// ============================================================
__global__ void ln_kernel(const float* __restrict__ in, float* __restrict__ out,
                          const float* __restrict__ sc, const float* __restrict__ bi) {
    int t = blockIdx.x;
    int d = threadIdx.x;
    float v = in[t*DD + d];
    float sum = v, sq = v*v;
    #pragma unroll
    for (int o = 16; o; o >>= 1) {
        sum += __shfl_xor_sync(0xffffffffu, sum, o);
        sq  += __shfl_xor_sync(0xffffffffu, sq,  o);
    }
    __shared__ float red0[8], red1[8];
    __shared__ float s_mean, s_rstd;
    int w = d >> 5, lane = d & 31;
    if (lane == 0) { red0[w] = sum; red1[w] = sq; }
    __syncthreads();
    if (w == 0) {
        float a = (lane < 8) ? red0[lane] : 0.f;
        float c = (lane < 8) ? red1[lane] : 0.f;
        #pragma unroll
        for (int o = 4; o; o >>= 1) {
            a += __shfl_xor_sync(0xffffffffu, a, o);
            c += __shfl_xor_sync(0xffffffffu, c, o);
        }
        if (lane == 0) {
            float mean = a * (1.0f/DD);
            float var  = c * (1.0f/DD) - mean*mean;
            s_mean = mean;
            s_rstd = rsqrtf(var + 1e-5f);
        }
    }
    __syncthreads();
    out[t*DD + d] = (v - s_mean) * s_rstd * sc[d] + bi[d];
}

// ============================================================
// GEMM: C[M,N] = act(A[M,K] @ B[K,N] + bias) (+ res)
// BM=64 BN=64 BK=16, 16x16 threads, 4x4 microtile
// ACT: 0 = none, 1 = relu
// ============================================================
template<int ACT>
__global__ void gemm_kernel(const float* __restrict__ A, const float* __restrict__ Bw,
                            const float* __restrict__ bias, const float* __restrict__ res,
                            float* __restrict__ C, int M, int N, int K) {
    __shared__ float As[64][17];
    __shared__ float Bs[16][64];
    const int tx = threadIdx.x, ty = threadIdx.y;
    const int tid = ty*16 + tx;
    const int m0 = blockIdx.x*64, n0 = blockIdx.y*64;

    float acc[4][4] = {};
    for (int k0 = 0; k0 < K; k0 += 16) {
        #pragma unroll
        for (int i = 0; i < 4; i++) {
            int idx = tid + 256*i;
            int r = idx >> 4, c = idx & 15;
            As[r][c] = A[(m0 + r)*K + k0 + c];
        }
        #pragma unroll
        for (int i = 0; i < 4; i++) {
            int idx = tid + 256*i;
            int r = idx >> 6, c = idx & 63;
            Bs[r][c] = Bw[(k0 + r)*N + n0 + c];
        }
        __syncthreads();
        #pragma unroll
        for (int k = 0; k < 16; k++) {
            float a[4];
            #pragma unroll
            for (int r = 0; r < 4; r++) a[r] = As[ty*4 + r][k];
            float4 bv = *(const float4*)&Bs[k][tx*4];
            float b4[4] = {bv.x, bv.y, bv.z, bv.w};
            #pragma unroll
            for (int r = 0; r < 4; r++)
                #pragma unroll
                for (int c = 0; c < 4; c++)
                    acc[r][c] = fmaf(a[r], b4[c], acc[r][c]);
        }
        __syncthreads();
    }
    #pragma unroll
    for (int r = 0; r < 4; r++) {
        int row = m0 + ty*4 + r;
        #pragma unroll
        for (int c = 0; c < 4; c++) {
            int col = n0 + tx*4 + c;
            float v = acc[r][c] + bias[col];
            if (ACT == 1) v = fmaxf(v, 0.f);
            if (res) v += res[row*N + col];
            C[row*N + col] = v;
        }
    }
}

// ============================================================
// Flash attention (fp32, online softmax)
// grid: (S/64, B*H); block 16x16
// Q tile 64x32, KV tiles 64x32, P staged via smem for PV
// ============================================================
__global__ void attn_kernel(const float* __restrict__ Qg, const float* __restrict__ Kg,
                            const float* __restrict__ Vg, float* __restrict__ Og) {
    __shared__ float Qs[64][DK+1];
    __shared__ float Ks[64][DK+1];
    __shared__ float Vs[64][DK+2];
    __shared__ float Ps[64][64];

    const int bh = blockIdx.y;
    const int b  = bh >> 3;
    const int h  = bh & 7;
    const int s0 = blockIdx.x * 64;
    const int tx = threadIdx.x, ty = threadIdx.y;
    const int tid = ty*16 + tx;

    const float* qbase = Qg + (size_t)(b*SS + s0)*DD + h*DK;
    #pragma unroll
    for (int i = 0; i < 8; i++) {
        int idx = tid + 256*i;           // 2048 elems
        int r = idx >> 5, c = idx & 31;
        Qs[r][c] = qbase[r*DD + c];
    }

    float m_i[4], l_i[4], oa[4][2];
    #pragma unroll
    for (int r = 0; r < 4; r++) { m_i[r] = -INFINITY; l_i[r] = 0.f; oa[r][0] = 0.f; oa[r][1] = 0.f; }
    __syncthreads();

    for (int kv0 = 0; kv0 < SS; kv0 += 64) {
        const float* kbase = Kg + (size_t)(b*SS + kv0)*DD + h*DK;
        const float* vbase = Vg + (size_t)(b*SS + kv0)*DD + h*DK;
        #pragma unroll
        for (int i = 0; i < 8; i++) {
            int idx = tid + 256*i;
            int r = idx >> 5, c = idx & 31;
            Ks[r][c] = kbase[r*DD + c];
            Vs[r][c] = vbase[r*DD + c];
        }
        __syncthreads();

        // scores: 64x64, 4x4 per thread
        float s[4][4] = {};
        #pragma unroll
        for (int d = 0; d < DK; d++) {
            float a[4], k4[4];
            #pragma unroll
            for (int r = 0; r < 4; r++) a[r]  = Qs[ty*4 + r][d];
            #pragma unroll
            for (int c = 0; c < 4; c++) k4[c] = Ks[tx*4 + c][d];
            #pragma unroll
            for (int r = 0; r < 4; r++)
                #pragma unroll
                for (int c = 0; c < 4; c++)
                    s[r][c] = fmaf(a[r], k4[c], s[r][c]);
        }

        // online softmax per row
        float alpha[4];
        #pragma unroll
        for (int r = 0; r < 4; r++) {
            float mt = fmaxf(fmaxf(s[r][0], s[r][1]), fmaxf(s[r][2], s[r][3])) * 1.0f;
            // scores not yet scaled: scale now
            mt = mt * SCALE;
            #pragma unroll
            for (int o = 8; o; o >>= 1)
                mt = fmaxf(mt, __shfl_xor_sync(0xffffffffu, mt, o));
            float mnew = fmaxf(m_i[r], mt);
            alpha[r] = __expf(m_i[r] - mnew);
            float rs = 0.f;
            #pragma unroll
            for (int c = 0; c < 4; c++) {
                float p = __expf(s[r][c]*SCALE - mnew);
                Ps[ty*4 + r][tx*4 + c] = p;
                rs += p;
            }
            #pragma unroll
            for (int o = 8; o; o >>= 1)
                rs += __shfl_xor_sync(0xffffffffu, rs, o);
            l_i[r] = l_i[r]*alpha[r] + rs;
            m_i[r] = mnew;
            oa[r][0] *= alpha[r];
            oa[r][1] *= alpha[r];
        }
        __syncthreads();

        // PV: O[64x32] += P[64x64] @ V[64x32]; thread owns 4 rows x 2 dims (d = tx*2..+1)
        #pragma unroll 4
        for (int j = 0; j < 64; j++) {
            float2 v2 = *(const float2*)&Vs[j][tx*2];
            #pragma unroll
            for (int r = 0; r < 4; r++) {
                float p = Ps[ty*4 + r][j];
                oa[r][0] = fmaf(p, v2.x, oa[r][0]);
                oa[r][1] = fmaf(p, v2.y, oa[r][1]);
            }
        }
        __syncthreads();
    }

    // write out
    #pragma unroll
    for (int r = 0; r < 4; r++) {
        float inv = 1.0f / l_i[r];
        int row = b*SS + s0 + ty*4 + r;
        float* op = Og + (size_t)row*DD + h*DK + tx*2;
        op[0] = oa[r][0] * inv;
        op[1] = oa[r][1] * inv;
    }
}

// ============================================================
// host orchestration
// ============================================================
extern "C" void kernel_launch(void* const* d_in, const int* in_sizes, int n_in,
                              void* d_out, int out_size) {
    const float* x     = (const float*)d_in[0];
    const float* ln0_s = (const float*)d_in[1];
    const float* ln0_b = (const float*)d_in[2];
    const float* ln1_s = (const float*)d_in[3];
    const float* ln1_b = (const float*)d_in[4];
    const float* ln2_s = (const float*)d_in[5];
    const float* ln2_b = (const float*)d_in[6];
    const float* wq = (const float*)d_in[7];
    const float* bq = (const float*)d_in[8];
    const float* wk = (const float*)d_in[9];
    const float* bk = (const float*)d_in[10];
    const float* wv = (const float*)d_in[11];
    const float* bv = (const float*)d_in[12];
    const float* wo = (const float*)d_in[13];
    const float* bo = (const float*)d_in[14];
    const float* w1 = (const float*)d_in[15];
    const float* b1 = (const float*)d_in[16];
    const float* w2 = (const float*)d_in[17];
    const float* b2 = (const float*)d_in[18];
    float* out = (float*)d_out;

    float *px, *px2, *pq, *pk, *pv, *po, *pff;
    cudaGetSymbolAddress((void**)&px,  g_x);
    cudaGetSymbolAddress((void**)&px2, g_x2);
    cudaGetSymbolAddress((void**)&pq,  g_q);
    cudaGetSymbolAddress((void**)&pk,  g_k);
    cudaGetSymbolAddress((void**)&pv,  g_v);
    cudaGetSymbolAddress((void**)&po,  g_o);
    cudaGetSymbolAddress((void**)&pff, g_ff);

    dim3 tb(16, 16);
    dim3 g_gemm_d (NTOK/64, DD/64);    // N=256
    dim3 g_gemm_ff(NTOK/64, FFD/64);   // N=512
    dim3 g_attn(SS/64, BB*HH);

    // leading LayerNorm
    ln_kernel<<<NTOK, 256>>>(x, px, ln0_s, ln0_b);

    for (int l = 0; l < LL; l++) {
        const float* l1s = ln1_s + l*DD; const float* l1b = ln1_b + l*DD;
        const float* l2s = ln2_s + l*DD; const float* l2b = ln2_b + l*DD;
        const float* Wq = wq + (size_t)l*DD*DD; const float* Bq = bq + l*DD;
        const float* Wk = wk + (size_t)l*DD*DD; const float* Bk = bk + l*DD;
        const float* Wv = wv + (size_t)l*DD*DD; const float* Bv = bv + l*DD;
        const float* Wo = wo + (size_t)l*DD*DD; const float* Bo = bo + l*DD;
        const float* W1 = w1 + (size_t)l*DD*FFD; const float* B1 = b1 + l*FFD;
        const float* W2 = w2 + (size_t)l*FFD*DD; const float* B2 = b2 + l*DD;

        // pre-norm attention
        ln_kernel<<<NTOK, 256>>>(px, px2, l1s, l1b);
        gemm_kernel<0><<<g_gemm_d, tb>>>(px2, Wq, Bq, nullptr, pq, NTOK, DD, DD);
        gemm_kernel<0><<<g_gemm_d, tb>>>(px2, Wk, Bk, nullptr, pk, NTOK, DD, DD);
        gemm_kernel<0><<<g_gemm_d, tb>>>(px2, Wv, Bv, nullptr, pv, NTOK, DD, DD);
        attn_kernel<<<g_attn, tb>>>(pq, pk, pv, po);
        gemm_kernel<0><<<g_gemm_d, tb>>>(po, Wo, Bo, px, px, NTOK, DD, DD);

        // pre-norm FFN
        ln_kernel<<<NTOK, 256>>>(px, px2, l2s, l2b);
        gemm_kernel<1><<<g_gemm_ff, tb>>>(px2, W1, B1, nullptr, pff, NTOK, FFD, DD);
        float* dst = (l == LL-1) ? out : px;
        gemm_kernel<0><<<g_gemm_d, tb>>>(pff, W2, B2, px, dst, NTOK, DD, FFD);
    }
}

// round 3
// speedup vs baseline: 1.9069x; 1.9069x over previous
#include <cuda_runtime.h>
#include <math.h>
#include <stdint.h>

// Problem constants
#define BB   4
#define SS   2048
#define DD   256
#define HH   8
#define LL   4
#define FFD  512
#define DK   32
#define NTOK (BB*SS)        // 8192
#define SCALE 0.17677669529663687f  // 1/sqrt(32)
#define LOG2E 1.4426950408889634f

// -------- device scratch (no allocations allowed) --------
__device__ float g_x [NTOK*DD];
__device__ float g_x2[NTOK*DD];
__device__ float g_q [NTOK*DD];
__device__ float g_k [NTOK*DD];
__device__ float g_v [NTOK*DD];
__device__ float g_o [NTOK*DD];
__device__ float g_ff[NTOK*FFD];
// transposed weights [N][K] per layer
__device__ float g_wqT[LL*DD*DD];
__device__ float g_wkT[LL*DD*DD];
__device__ float g_wvT[LL*DD*DD];
__device__ float g_woT[LL*DD*DD];
__device__ float g_w1T[LL*DD*FFD];
__device__ float g_w2T[LL*FFD*DD];

// ============================================================
// tf32 helpers (plain sm_80+ PTX — no 'a' feature gating)
// ============================================================
__device__ __forceinline__ uint32_t f2tf(float f) {
    uint32_t u;
    asm("cvt.rna.tf32.f32 %0, %1;" : "=r"(u) : "f"(f));
    return u;
}
// D += A(16x8) * B(8x8), tf32 in, f32 accum
__device__ __forceinline__ void mma8(float* d, const uint32_t* a, uint32_t b0, uint32_t b1) {
    asm volatile(
        "mma.sync.aligned.m16n8k8.row.col.f32.tf32.tf32.f32 "
        "{%0,%1,%2,%3}, {%4,%5,%6,%7}, {%8,%9}, {%0,%1,%2,%3};"
        : "+f"(d[0]), "+f"(d[1]), "+f"(d[2]), "+f"(d[3])
        : "r"(a[0]), "r"(a[1]), "r"(a[2]), "r"(a[3]), "r"(b0), "r"(b1));
}

// ============================================================
// Weight transpose: in [z][K][N] -> out [z][N][K]
// ============================================================
__global__ void transpose_k(const float* __restrict__ in, float* __restrict__ out, int K, int N) {
    __shared__ float t[32][33];
    const size_t zoff = (size_t)blockIdx.z * K * N;
    const float* src = in + zoff;
    float* dst = out + zoff;
    int n = blockIdx.x * 32 + threadIdx.x;
    int k0 = blockIdx.y * 32;
    #pragma unroll
    for (int j = threadIdx.y; j < 32; j += 8)
        t[j][threadIdx.x] = src[(size_t)(k0 + j) * N + n];
    __syncthreads();
    int k = k0 + threadIdx.x;
    int nb = blockIdx.x * 32;
    #pragma unroll
    for (int j = threadIdx.y; j < 32; j += 8)
        dst[(size_t)(nb + j) * K + k] = t[threadIdx.x][j];
}

// ============================================================
// tf32 mma GEMM: C[M,N] = act(A[M,K] @ Wt^T + bias) (+res)
// Wt is [N][K]. CTA tile 128x128, BK=32, 8 warps (warp tile 64x32).
// ============================================================
template<int N, int K, int ACT, bool RES>
__global__ void __launch_bounds__(256) mma_gemm(
    const float* __restrict__ A, const float* __restrict__ Wt,
    const float* __restrict__ bias, const float* __restrict__ res,
    float* __restrict__ C)
{
    __shared__ uint32_t As[128][33];
    __shared__ uint32_t Bs[128][33];

    const int tid = threadIdx.x;
    const int wid = tid >> 5, lane = tid & 31;
    const int g = lane >> 2, c = lane & 3;
    const int m0 = blockIdx.x * 128, n0 = blockIdx.y * 128;
    const int wm = (wid & 1) * 64;    // warp row base (2 warps in m)
    const int wn = (wid >> 1) * 32;   // warp col base (4 warps in n)

    float acc[4][4][4] = {};

    for (int kc = 0; kc < K; kc += 32) {
        // stage 128x32 of A and Wt into smem, converting to tf32
        #pragma unroll
        for (int i = 0; i < 4; i++) {
            int idx = tid + 256 * i;          // 1024 float4 slots
            int r = idx >> 3, c4 = idx & 7;
            float4 va = *(const float4*)(A  + (size_t)(m0 + r) * K + kc + c4 * 4);
            float4 vb = *(const float4*)(Wt + (size_t)(n0 + r) * K + kc + c4 * 4);
            uint32_t* pa = &As[r][c4 * 4];
            uint32_t* pb = &Bs[r][c4 * 4];
            pa[0] = f2tf(va.x); pa[1] = f2tf(va.y); pa[2] = f2tf(va.z); pa[3] = f2tf(va.w);
            pb[0] = f2tf(vb.x); pb[1] = f2tf(vb.y); pb[2] = f2tf(vb.z); pb[3] = f2tf(vb.w);
        }
        __syncthreads();

        #pragma unroll
        for (int k8 = 0; k8 < 4; k8++) {
            uint32_t a[4][4];
            #pragma unroll
            for (int mf = 0; mf < 4; mf++) {
                int rb = wm + mf * 16;
                a[mf][0] = As[rb + g    ][k8 * 8 + c    ];
                a[mf][1] = As[rb + g + 8][k8 * 8 + c    ];
                a[mf][2] = As[rb + g    ][k8 * 8 + c + 4];
                a[mf][3] = As[rb + g + 8][k8 * 8 + c + 4];
            }
            #pragma unroll
            for (int nf = 0; nf < 4; nf++) {
                uint32_t b0 = Bs[wn + nf * 8 + g][k8 * 8 + c    ];
                uint32_t b1 = Bs[wn + nf * 8 + g][k8 * 8 + c + 4];
                #pragma unroll
                for (int mf = 0; mf < 4; mf++)
                    mma8(acc[mf][nf], a[mf], b0, b1);
            }
        }
        __syncthreads();
    }

    // epilogue
    #pragma unroll
    for (int nf = 0; nf < 4; nf++) {
        int col = n0 + wn + nf * 8 + 2 * c;
        float2 bb = *(const float2*)(bias + col);
        #pragma unroll
        for (int mf = 0; mf < 4; mf++) {
            #pragma unroll
            for (int half = 0; half < 2; half++) {
                int row = m0 + wm + mf * 16 + g + half * 8;
                float vx = acc[mf][nf][half * 2 + 0] + bb.x;
                float vy = acc[mf][nf][half * 2 + 1] + bb.y;
                if (ACT == 1) { vx = fmaxf(vx, 0.f); vy = fmaxf(vy, 0.f); }
                if (RES) {
                    float2 r2 = *(const float2*)(res + (size_t)row * N + col);
                    vx += r2.x; vy += r2.y;
                }
                float2 o2 = {vx, vy};
                *(float2*)(C + (size_t)row * N + col) = o2;
            }
        }
    }
}

// ============================================================
// Flash attention with tf32 mma.
// Block: 128 thr (4 warps). Q tile 64, KV tile 64. Warp owns 16 Q rows.
// Q pre-scaled by SCALE*log2(e); softmax in base-2.
// ============================================================
__global__ void __launch_bounds__(128) attn_mma(
    const float* __restrict__ Qg, const float* __restrict__ Kg,
    const float* __restrict__ Vg, float* __restrict__ Og)
{
    __shared__ uint32_t Qs[64][33];
    __shared__ uint32_t Ks[64][33];
    __shared__ uint32_t Vs[64][40];
    __shared__ uint32_t Ps[64][68];

    const int tid = threadIdx.x;
    const int wid = tid >> 5, lane = tid & 31;
    const int g = lane >> 2, c = lane & 3;
    const int bh = blockIdx.y;
    const int b = bh >> 3, h = bh & 7;
    const int s0 = blockIdx.x * 64;
    const float SC2 = SCALE * LOG2E;

    // load Q tile (scaled, tf32)
    #pragma unroll
    for (int i = 0; i < 4; i++) {
        int idx = tid + 128 * i;          // 512 float4 slots = 64x32
        int r = idx >> 3, c4 = idx & 7;
        float4 v = *(const float4*)(Qg + (size_t)(b * SS + s0 + r) * DD + h * DK + c4 * 4);
        uint32_t* p = &Qs[r][c4 * 4];
        p[0] = f2tf(v.x * SC2); p[1] = f2tf(v.y * SC2);
        p[2] = f2tf(v.z * SC2); p[3] = f2tf(v.w * SC2);
    }

    float m_i[2] = {-INFINITY, -INFINITY};
    float l_i[2] = {0.f, 0.f};
    float o[4][4] = {};
    __syncthreads();

    for (int kv0 = 0; kv0 < SS; kv0 += 64) {
        // load K, V tiles (tf32)
        #pragma unroll
        for (int i = 0; i < 4; i++) {
            int idx = tid + 128 * i;
            int r = idx >> 3, c4 = idx & 7;
            const size_t base = (size_t)(b * SS + kv0 + r) * DD + h * DK + c4 * 4;
            float4 kv4 = *(const float4*)(Kg + base);
            float4 vv4 = *(const float4*)(Vg + base);
            uint32_t* pk = &Ks[r][c4 * 4];
            uint32_t* pv = &Vs[r][c4 * 4];
            pk[0] = f2tf(kv4.x); pk[1] = f2tf(kv4.y); pk[2] = f2tf(kv4.z); pk[3] = f2tf(kv4.w);
            pv[0] = f2tf(vv4.x); pv[1] = f2tf(vv4.y); pv[2] = f2tf(vv4.z); pv[3] = f2tf(vv4.w);
        }
        __syncthreads();

        // S = Q @ K^T  (warp's 16 rows x 64 cols)
        float s[8][4] = {};
        #pragma unroll
        for (int k8 = 0; k8 < 4; k8++) {
            uint32_t a[4];
            a[0] = Qs[wid * 16 + g    ][k8 * 8 + c    ];
            a[1] = Qs[wid * 16 + g + 8][k8 * 8 + c    ];
            a[2] = Qs[wid * 16 + g    ][k8 * 8 + c + 4];
            a[3] = Qs[wid * 16 + g + 8][k8 * 8 + c + 4];
            #pragma unroll
            for (int nf = 0; nf < 8; nf++) {
                uint32_t b0 = Ks[nf * 8 + g][k8 * 8 + c    ];
                uint32_t b1 = Ks[nf * 8 + g][k8 * 8 + c + 4];
                mma8(s[nf], a, b0, b1);
            }
        }

        // online softmax (base-2 domain)
        float mt0 = -INFINITY, mt1 = -INFINITY;
        #pragma unroll
        for (int nf = 0; nf < 8; nf++) {
            mt0 = fmaxf(mt0, fmaxf(s[nf][0], s[nf][1]));
            mt1 = fmaxf(mt1, fmaxf(s[nf][2], s[nf][3]));
        }
        #pragma unroll
        for (int off = 1; off <= 2; off <<= 1) {
            mt0 = fmaxf(mt0, __shfl_xor_sync(0xffffffffu, mt0, off));
            mt1 = fmaxf(mt1, __shfl_xor_sync(0xffffffffu, mt1, off));
        }
        float mn0 = fmaxf(m_i[0], mt0);
        float mn1 = fmaxf(m_i[1], mt1);
        float al0 = exp2f(m_i[0] - mn0);
        float al1 = exp2f(m_i[1] - mn1);
        m_i[0] = mn0; m_i[1] = mn1;

        float rs0 = 0.f, rs1 = 0.f;
        #pragma unroll
        for (int nf = 0; nf < 8; nf++) {
            float p00 = exp2f(s[nf][0] - mn0);
            float p01 = exp2f(s[nf][1] - mn0);
            float p10 = exp2f(s[nf][2] - mn1);
            float p11 = exp2f(s[nf][3] - mn1);
            rs0 += p00 + p01;
            rs1 += p10 + p11;
            Ps[wid * 16 + g    ][nf * 8 + 2 * c    ] = f2tf(p00);
            Ps[wid * 16 + g    ][nf * 8 + 2 * c + 1] = f2tf(p01);
            Ps[wid * 16 + g + 8][nf * 8 + 2 * c    ] = f2tf(p10);
            Ps[wid * 16 + g + 8][nf * 8 + 2 * c + 1] = f2tf(p11);
        }
        #pragma unroll
        for (int off = 1; off <= 2; off <<= 1) {
            rs0 += __shfl_xor_sync(0xffffffffu, rs0, off);
            rs1 += __shfl_xor_sync(0xffffffffu, rs1, off);
        }
        l_i[0] = l_i[0] * al0 + rs0;
        l_i[1] = l_i[1] * al1 + rs1;
        #pragma unroll
        for (int nf = 0; nf < 4; nf++) {
            o[nf][0] *= al0; o[nf][1] *= al0;
            o[nf][2] *= al1; o[nf][3] *= al1;
        }
        __syncwarp();

        // O += P @ V  (P rows are warp-private)
        #pragma unroll
        for (int k8 = 0; k8 < 8; k8++) {
            uint32_t a[4];
            a[0] = Ps[wid * 16 + g    ][k8 * 8 + c    ];
            a[1] = Ps[wid * 16 + g + 8][k8 * 8 + c    ];
            a[2] = Ps[wid * 16 + g    ][k8 * 8 + c + 4];
            a[3] = Ps[wid * 16 + g + 8][k8 * 8 + c + 4];
            #pragma unroll
            for (int nf = 0; nf < 4; nf++) {
                uint32_t b0 = Vs[k8 * 8 + c    ][nf * 8 + g];
                uint32_t b1 = Vs[k8 * 8 + c + 4][nf * 8 + g];
                mma8(o[nf], a, b0, b1);
            }
        }
        __syncthreads();
    }

    // write O
    float inv0 = 1.f / l_i[0];
    float inv1 = 1.f / l_i[1];
    #pragma unroll
    for (int nf = 0; nf < 4; nf++) {
        int col = h * DK + nf * 8 + 2 * c;
        int row0 = b * SS + s0 + wid * 16 + g;
        float2 v0 = {o[nf][0] * inv0, o[nf][1] * inv0};
        float2 v1 = {o[nf][2] * inv1, o[nf][3] * inv1};
        *(float2*)(Og + (size_t)row0 * DD + col)       = v0;
        *(float2*)(Og + (size_t)(row0 + 8) * DD + col) = v1;
    }
}

// ============================================================
// LayerNorm: one block per token, 256 threads (= D)
// ============================================================
__global__ void ln_kernel(const float* __restrict__ in, float* __restrict__ out,
                          const float* __restrict__ sc, const float* __restrict__ bi) {
    int t = blockIdx.x;
    int d = threadIdx.x;
    float v = in[t*DD + d];
    float sum = v, sq = v*v;
    #pragma unroll
    for (int o = 16; o; o >>= 1) {
        sum += __shfl_xor_sync(0xffffffffu, sum, o);
        sq  += __shfl_xor_sync(0xffffffffu, sq,  o);
    }
    __shared__ float red0[8], red1[8];
    __shared__ float s_mean, s_rstd;
    int w = d >> 5, lane = d & 31;
    if (lane == 0) { red0[w] = sum; red1[w] = sq; }
    __syncthreads();
    if (w == 0) {
        float a = (lane < 8) ? red0[lane] : 0.f;
        float c = (lane < 8) ? red1[lane] : 0.f;
        #pragma unroll
        for (int o = 4; o; o >>= 1) {
            a += __shfl_xor_sync(0xffffffffu, a, o);
            c += __shfl_xor_sync(0xffffffffu, c, o);
        }
        if (lane == 0) {
            float mean = a * (1.0f/DD);
            float var  = c * (1.0f/DD) - mean*mean;
            s_mean = mean;
            s_rstd = rsqrtf(var + 1e-5f);
        }
    }
    __syncthreads();
    out[t*DD + d] = (v - s_mean) * s_rstd * sc[d] + bi[d];
}

// ============================================================
// host orchestration
// ============================================================
extern "C" void kernel_launch(void* const* d_in, const int* in_sizes, int n_in,
                              void* d_out, int out_size) {
    const float* x     = (const float*)d_in[0];
    const float* ln0_s = (const float*)d_in[1];
    const float* ln0_b = (const float*)d_in[2];
    const float* ln1_s = (const float*)d_in[3];
    const float* ln1_b = (const float*)d_in[4];
    const float* ln2_s = (const float*)d_in[5];
    const float* ln2_b = (const float*)d_in[6];
    const float* wq = (const float*)d_in[7];
    const float* bq = (const float*)d_in[8];
    const float* wk = (const float*)d_in[9];
    const float* bk = (const float*)d_in[10];
    const float* wv = (const float*)d_in[11];
    const float* bv = (const float*)d_in[12];
    const float* wo = (const float*)d_in[13];
    const float* bo = (const float*)d_in[14];
    const float* w1 = (const float*)d_in[15];
    const float* b1 = (const float*)d_in[16];
    const float* w2 = (const float*)d_in[17];
    const float* b2 = (const float*)d_in[18];
    float* out = (float*)d_out;

    float *px, *px2, *pq, *pk, *pv, *po, *pff;
    float *pwqT, *pwkT, *pwvT, *pwoT, *pw1T, *pw2T;
    cudaGetSymbolAddress((void**)&px,  g_x);
    cudaGetSymbolAddress((void**)&px2, g_x2);
    cudaGetSymbolAddress((void**)&pq,  g_q);
    cudaGetSymbolAddress((void**)&pk,  g_k);
    cudaGetSymbolAddress((void**)&pv,  g_v);
    cudaGetSymbolAddress((void**)&po,  g_o);
    cudaGetSymbolAddress((void**)&pff, g_ff);
    cudaGetSymbolAddress((void**)&pwqT, g_wqT);
    cudaGetSymbolAddress((void**)&pwkT, g_wkT);
    cudaGetSymbolAddress((void**)&pwvT, g_wvT);
    cudaGetSymbolAddress((void**)&pwoT, g_woT);
    cudaGetSymbolAddress((void**)&pw1T, g_w1T);
    cudaGetSymbolAddress((void**)&pw2T, g_w2T);

    dim3 tt(32, 8);
    transpose_k<<<dim3(DD/32,  DD/32,  LL), tt>>>(wq, pwqT, DD, DD);
    transpose_k<<<dim3(DD/32,  DD/32,  LL), tt>>>(wk, pwkT, DD, DD);
    transpose_k<<<dim3(DD/32,  DD/32,  LL), tt>>>(wv, pwvT, DD, DD);
    transpose_k<<<dim3(DD/32,  DD/32,  LL), tt>>>(wo, pwoT, DD, DD);
    transpose_k<<<dim3(FFD/32, DD/32,  LL), tt>>>(w1, pw1T, DD, FFD);
    transpose_k<<<dim3(DD/32,  FFD/32, LL), tt>>>(w2, pw2T, FFD, DD);

    dim3 g_d  (NTOK/128, DD/128);    // (64, 2)
    dim3 g_ff1(NTOK/128, FFD/128);   // (64, 4)
    dim3 g_attn(SS/64, BB*HH);

    ln_kernel<<<NTOK, 256>>>(x, px, ln0_s, ln0_b);

    for (int l = 0; l < LL; l++) {
        const float* l1s = ln1_s + l*DD; const float* l1b = ln1_b + l*DD;
        const float* l2s = ln2_s + l*DD; const float* l2b = ln2_b + l*DD;
        const float* WqT = pwqT + (size_t)l*DD*DD;  const float* Bq = bq + l*DD;
        const float* WkT = pwkT + (size_t)l*DD*DD;  const float* Bk = bk + l*DD;
        const float* WvT = pwvT + (size_t)l*DD*DD;  const float* Bv = bv + l*DD;
        const float* WoT = pwoT + (size_t)l*DD*DD;  const float* Bo = bo + l*DD;
        const float* W1T = pw1T + (size_t)l*DD*FFD; const float* B1 = b1 + l*FFD;
        const float* W2T = pw2T + (size_t)l*FFD*DD; const float* B2 = b2 + l*DD;

        ln_kernel<<<NTOK, 256>>>(px, px2, l1s, l1b);
        mma_gemm<DD, DD, 0, false><<<g_d, 256>>>(px2, WqT, Bq, nullptr, pq);
        mma_gemm<DD, DD, 0, false><<<g_d, 256>>>(px2, WkT, Bk, nullptr, pk);
        mma_gemm<DD, DD, 0, false><<<g_d, 256>>>(px2, WvT, Bv, nullptr, pv);
        attn_mma<<<g_attn, 128>>>(pq, pk, pv, po);
        mma_gemm<DD, DD, 0, true><<<g_d, 256>>>(po, WoT, Bo, px, px);

        ln_kernel<<<NTOK, 256>>>(px, px2, l2s, l2b);
        mma_gemm<FFD, DD, 1, false><<<g_ff1, 256>>>(px2, W1T, B1, nullptr, pff);
        float* dst = (l == LL-1) ? out : px;
        mma_gemm<DD, FFD, 0, true><<<g_d, 256>>>(pff, W2T, B2, px, dst);
    }
}

// round 4
// speedup vs baseline: 2.4807x; 1.3009x over previous
#include <cuda_runtime.h>
#include <math.h>
#include <stdint.h>

// Problem constants
#define BB   4
#define SS   2048
#define DD   256
#define HH   8
#define LL   4
#define FFD  512
#define DK   32
#define NTOK (BB*SS)        // 8192
#define QKVN 768
#define SCALE 0.17677669529663687f  // 1/sqrt(32)
#define LOG2E 1.4426950408889634f

// -------- device scratch (no allocations allowed) --------
__device__ float g_x  [NTOK*DD];
__device__ float g_x2 [NTOK*DD];
__device__ float g_qkv[NTOK*QKVN];
__device__ float g_o  [NTOK*DD];
__device__ float g_ff [NTOK*FFD];
// transposed weights
__device__ float g_wqkvT[LL*QKVN*DD];   // rows 0-255: q, 256-511: k, 512-767: v
__device__ float g_bqkv [LL*QKVN];
__device__ float g_woT[LL*DD*DD];
__device__ float g_w1T[LL*DD*FFD];
__device__ float g_w2T[LL*FFD*DD];

// ============================================================
// helpers
// ============================================================
__device__ __forceinline__ uint32_t f2tf(float f) {
    uint32_t u;
    asm("cvt.rna.tf32.f32 %0, %1;" : "=r"(u) : "f"(f));
    return u;
}
__device__ __forceinline__ uint32_t fu(float f) { return __float_as_uint(f); }

// D += A(16x8) * B(8x8), tf32 in, f32 accum
__device__ __forceinline__ void mma8(float* d, const uint32_t* a, uint32_t b0, uint32_t b1) {
    asm volatile(
        "mma.sync.aligned.m16n8k8.row.col.f32.tf32.tf32.f32 "
        "{%0,%1,%2,%3}, {%4,%5,%6,%7}, {%8,%9}, {%0,%1,%2,%3};"
        : "+f"(d[0]), "+f"(d[1]), "+f"(d[2]), "+f"(d[3])
        : "r"(a[0]), "r"(a[1]), "r"(a[2]), "r"(a[3]), "r"(b0), "r"(b1));
}
__device__ __forceinline__ uint32_t smem_u32(const void* p) {
    uint32_t a;
    asm("{ .reg .u64 t; cvta.to.shared.u64 t, %1; cvt.u32.u64 %0, t; }" : "=r"(a) : "l"(p));
    return a;
}
__device__ __forceinline__ void cpa16(uint32_t saddr, const void* g) {
    asm volatile("cp.async.ca.shared.global [%0], [%1], 16;" :: "r"(saddr), "l"(g));
}
#define CPA_COMMIT() asm volatile("cp.async.commit_group;" ::: "memory")
#define CPA_WAIT0()  asm volatile("cp.async.wait_group 0;" ::: "memory")

// ============================================================
// Weight transpose: in [z][K][N] -> out rows [z*layerRows + rowoff + n][K]
// ============================================================
__global__ void transpose_k2(const float* __restrict__ in, float* __restrict__ out,
                             int K, int N, int layerRows, int rowoff) {
    __shared__ float t[32][33];
    const float* src = in + (size_t)blockIdx.z * K * N;
    int n = blockIdx.x * 32 + threadIdx.x;
    int k0 = blockIdx.y * 32;
    #pragma unroll
    for (int j = threadIdx.y; j < 32; j += 8)
        t[j][threadIdx.x] = src[(size_t)(k0 + j) * N + n];
    __syncthreads();
    int k = k0 + threadIdx.x;
    int nb = blockIdx.x * 32;
    #pragma unroll
    for (int j = threadIdx.y; j < 32; j += 8)
        out[((size_t)blockIdx.z * layerRows + rowoff + nb + j) * K + k] = t[threadIdx.x][j];
}

__global__ void concat_bias(const float* __restrict__ bq, const float* __restrict__ bk,
                            const float* __restrict__ bv, float* __restrict__ dst) {
    int l = blockIdx.x, d = threadIdx.x;
    dst[l*QKVN + d]       = bq[l*DD + d];
    dst[l*QKVN + 256 + d] = bk[l*DD + d];
    dst[l*QKVN + 512 + d] = bv[l*DD + d];
}

// ============================================================
// tf32 mma GEMM: C[M,N] = act(A[M,K] @ Wt^T + bias) (+res)
// Wt is [N][K]. CTA tile 128x128, BK=32, 8 warps (warp tile 64x32).
// ============================================================
template<int N, int K, int ACT, bool RES>
__global__ void __launch_bounds__(256) mma_gemm(
    const float* __restrict__ A, const float* __restrict__ Wt,
    const float* __restrict__ bias, const float* __restrict__ res,
    float* __restrict__ C)
{
    __shared__ uint32_t As[128][33];
    __shared__ uint32_t Bs[128][33];

    const int tid = threadIdx.x;
    const int wid = tid >> 5, lane = tid & 31;
    const int g = lane >> 2, c = lane & 3;
    const int m0 = blockIdx.x * 128, n0 = blockIdx.y * 128;
    const int wm = (wid & 1) * 64;
    const int wn = (wid >> 1) * 32;

    float acc[4][4][4] = {};

    for (int kc = 0; kc < K; kc += 32) {
        #pragma unroll
        for (int i = 0; i < 4; i++) {
            int idx = tid + 256 * i;
            int r = idx >> 3, c4 = idx & 7;
            float4 va = *(const float4*)(A  + (size_t)(m0 + r) * K + kc + c4 * 4);
            float4 vb = *(const float4*)(Wt + (size_t)(n0 + r) * K + kc + c4 * 4);
            uint32_t* pa = &As[r][c4 * 4];
            uint32_t* pb = &Bs[r][c4 * 4];
            pa[0] = f2tf(va.x); pa[1] = f2tf(va.y); pa[2] = f2tf(va.z); pa[3] = f2tf(va.w);
            pb[0] = f2tf(vb.x); pb[1] = f2tf(vb.y); pb[2] = f2tf(vb.z); pb[3] = f2tf(vb.w);
        }
        __syncthreads();

        #pragma unroll
        for (int k8 = 0; k8 < 4; k8++) {
            uint32_t a[4][4];
            #pragma unroll
            for (int mf = 0; mf < 4; mf++) {
                int rb = wm + mf * 16;
                a[mf][0] = As[rb + g    ][k8 * 8 + c    ];
                a[mf][1] = As[rb + g + 8][k8 * 8 + c    ];
                a[mf][2] = As[rb + g    ][k8 * 8 + c + 4];
                a[mf][3] = As[rb + g + 8][k8 * 8 + c + 4];
            }
            #pragma unroll
            for (int nf = 0; nf < 4; nf++) {
                uint32_t b0 = Bs[wn + nf * 8 + g][k8 * 8 + c    ];
                uint32_t b1 = Bs[wn + nf * 8 + g][k8 * 8 + c + 4];
                #pragma unroll
                for (int mf = 0; mf < 4; mf++)
                    mma8(acc[mf][nf], a[mf], b0, b1);
            }
        }
        __syncthreads();
    }

    #pragma unroll
    for (int nf = 0; nf < 4; nf++) {
        int col = n0 + wn + nf * 8 + 2 * c;
        float2 bb = *(const float2*)(bias + col);
        #pragma unroll
        for (int mf = 0; mf < 4; mf++) {
            #pragma unroll
            for (int half = 0; half < 2; half++) {
                int row = m0 + wm + mf * 16 + g + half * 8;
                float vx = acc[mf][nf][half * 2 + 0] + bb.x;
                float vy = acc[mf][nf][half * 2 + 1] + bb.y;
                if (ACT == 1) { vx = fmaxf(vx, 0.f); vy = fmaxf(vy, 0.f); }
                if (RES) {
                    float2 r2 = *(const float2*)(res + (size_t)row * N + col);
                    vx += r2.x; vy += r2.y;
                }
                float2 o2 = {vx, vy};
                *(float2*)(C + (size_t)row * N + col) = o2;
            }
        }
    }
}

// ============================================================
// Flash attention v2 (tf32 mma, Q in regs, P via shuffles,
// cp.async double-buffered K/V). 256 thr, Q tile 128, KV tile 64.
// Q/K/V rows have stride QKVN (fused qkv buffer).
// ============================================================
__global__ void __launch_bounds__(256) attn_mma2(
    const float* __restrict__ Qg, const float* __restrict__ Kg,
    const float* __restrict__ Vg, float* __restrict__ Og)
{
    __shared__ float Ks[2][64][36];
    __shared__ float Vs[2][64][36];

    const int tid = threadIdx.x;
    const int wid = tid >> 5, lane = tid & 31;
    const int g = lane >> 2, c = lane & 3;
    const int bh = blockIdx.y;
    const int b = bh >> 3, h = bh & 7;
    const int s0 = blockIdx.x * 128;
    const int wq0 = wid * 16;
    const float SC2 = SCALE * LOG2E;

    const uint32_t sKs = smem_u32(&Ks[0][0][0]);
    const uint32_t sVs = smem_u32(&Vs[0][0][0]);

    // Q fragments in registers (rows wq0+g / wq0+g+8, cols k8*8+{c,c+4})
    uint32_t qa[4][4];
    {
        const float* qb = Qg + (size_t)(b * SS + s0 + wq0) * QKVN + h * DK;
        #pragma unroll
        for (int k8 = 0; k8 < 4; k8++) {
            qa[k8][0] = fu(qb[(size_t)g       * QKVN + k8 * 8 + c    ] * SC2);
            qa[k8][1] = fu(qb[(size_t)(g + 8) * QKVN + k8 * 8 + c    ] * SC2);
            qa[k8][2] = fu(qb[(size_t)g       * QKVN + k8 * 8 + c + 4] * SC2);
            qa[k8][3] = fu(qb[(size_t)(g + 8) * QKVN + k8 * 8 + c + 4] * SC2);
        }
    }

    float m0v = -INFINITY, m1v = -INFINITY;
    float l0 = 0.f, l1 = 0.f;
    float o[4][4] = {};

    // stage tile 0 into buffer 0
    {
        #pragma unroll
        for (int i = tid; i < 512; i += 256) {
            int r = i >> 3, j = i & 7;
            const size_t gbase = (size_t)(b * SS + r) * QKVN + h * DK + j * 4;
            uint32_t soff = (uint32_t)((r * 36 + j * 4) * 4);
            cpa16(sKs + soff, Kg + gbase);
            cpa16(sVs + soff, Vg + gbase);
        }
        CPA_COMMIT();
    }

    for (int t = 0; t < SS / 64; t++) {
        const int bf = t & 1;
        CPA_WAIT0();
        __syncthreads();

        if (t + 1 < SS / 64) {
            const int kv0 = (t + 1) * 64;
            const int nbf = bf ^ 1;
            #pragma unroll
            for (int i = tid; i < 512; i += 256) {
                int r = i >> 3, j = i & 7;
                const size_t gbase = (size_t)(b * SS + kv0 + r) * QKVN + h * DK + j * 4;
                uint32_t soff = (uint32_t)(((nbf * 64 + r) * 36 + j * 4) * 4);
                cpa16(sKs + soff, Kg + gbase);
                cpa16(sVs + soff, Vg + gbase);
            }
            CPA_COMMIT();
        }

        // ---- S = Q @ K^T : warp's 16 rows x 64 cols ----
        float s[8][4] = {};
        #pragma unroll
        for (int k8 = 0; k8 < 4; k8++) {
            #pragma unroll
            for (int nf = 0; nf < 8; nf++) {
                uint32_t b0 = fu(Ks[bf][nf * 8 + g][k8 * 8 + c    ]);
                uint32_t b1 = fu(Ks[bf][nf * 8 + g][k8 * 8 + c + 4]);
                mma8(s[nf], qa[k8], b0, b1);
            }
        }

        // ---- online softmax (base-2) ----
        float mt0 = -INFINITY, mt1 = -INFINITY;
        #pragma unroll
        for (int nf = 0; nf < 8; nf++) {
            mt0 = fmaxf(mt0, fmaxf(s[nf][0], s[nf][1]));
            mt1 = fmaxf(mt1, fmaxf(s[nf][2], s[nf][3]));
        }
        #pragma unroll
        for (int off = 1; off <= 2; off <<= 1) {
            mt0 = fmaxf(mt0, __shfl_xor_sync(0xffffffffu, mt0, off));
            mt1 = fmaxf(mt1, __shfl_xor_sync(0xffffffffu, mt1, off));
        }
        float mn0 = fmaxf(m0v, mt0);
        float mn1 = fmaxf(m1v, mt1);
        float al0 = exp2f(m0v - mn0);
        float al1 = exp2f(m1v - mn1);
        m0v = mn0; m1v = mn1;

        float rs0 = 0.f, rs1 = 0.f;
        #pragma unroll
        for (int nf = 0; nf < 8; nf++) {
            s[nf][0] = exp2f(s[nf][0] - mn0);
            s[nf][1] = exp2f(s[nf][1] - mn0);
            s[nf][2] = exp2f(s[nf][2] - mn1);
            s[nf][3] = exp2f(s[nf][3] - mn1);
            rs0 += s[nf][0] + s[nf][1];
            rs1 += s[nf][2] + s[nf][3];
        }
        #pragma unroll
        for (int off = 1; off <= 2; off <<= 1) {
            rs0 += __shfl_xor_sync(0xffffffffu, rs0, off);
            rs1 += __shfl_xor_sync(0xffffffffu, rs1, off);
        }
        l0 = l0 * al0 + rs0;
        l1 = l1 * al1 + rs1;
        #pragma unroll
        for (int nf = 0; nf < 4; nf++) {
            o[nf][0] *= al0; o[nf][1] *= al0;
            o[nf][2] *= al1; o[nf][3] *= al1;
        }

        // ---- O += P @ V (P converted accum->A-frag via quad shuffles) ----
        const int srcA = (lane & ~3) | (c >> 1);
        const int srcB = srcA + 2;
        const bool odd = (c & 1);
        #pragma unroll
        for (int k8 = 0; k8 < 8; k8++) {
            float x0 = __shfl_sync(0xffffffffu, s[k8][0], srcA);
            float x1 = __shfl_sync(0xffffffffu, s[k8][1], srcA);
            float y0 = __shfl_sync(0xffffffffu, s[k8][0], srcB);
            float y1 = __shfl_sync(0xffffffffu, s[k8][1], srcB);
            float z0 = __shfl_sync(0xffffffffu, s[k8][2], srcA);
            float z1 = __shfl_sync(0xffffffffu, s[k8][3], srcA);
            float w0 = __shfl_sync(0xffffffffu, s[k8][2], srcB);
            float w1 = __shfl_sync(0xffffffffu, s[k8][3], srcB);
            uint32_t a[4];
            a[0] = fu(odd ? x1 : x0);   // P[g,     k8*8+c  ]
            a[1] = fu(odd ? z1 : z0);   // P[g+8,   k8*8+c  ]
            a[2] = fu(odd ? y1 : y0);   // P[g,     k8*8+c+4]
            a[3] = fu(odd ? w1 : w0);   // P[g+8,   k8*8+c+4]
            #pragma unroll
            for (int nf = 0; nf < 4; nf++) {
                uint32_t b0 = fu(Vs[bf][k8 * 8 + c    ][nf * 8 + g]);
                uint32_t b1 = fu(Vs[bf][k8 * 8 + c + 4][nf * 8 + g]);
                mma8(o[nf], a, b0, b1);
            }
        }
    }

    // ---- write O (stride DD) ----
    float inv0 = 1.f / l0;
    float inv1 = 1.f / l1;
    const int row0 = b * SS + s0 + wq0 + g;
    #pragma unroll
    for (int nf = 0; nf < 4; nf++) {
        int col = h * DK + nf * 8 + 2 * c;
        float2 v0 = {o[nf][0] * inv0, o[nf][1] * inv0};
        float2 v1 = {o[nf][2] * inv1, o[nf][3] * inv1};
        *(float2*)(Og + (size_t)row0 * DD + col)       = v0;
        *(float2*)(Og + (size_t)(row0 + 8) * DD + col) = v1;
    }
}

// ============================================================
// LayerNorm: one block per token, 256 threads (= D)
// ============================================================
__global__ void ln_kernel(const float* __restrict__ in, float* __restrict__ out,
                          const float* __restrict__ sc, const float* __restrict__ bi) {
    int t = blockIdx.x;
    int d = threadIdx.x;
    float v = in[t*DD + d];
    float sum = v, sq = v*v;
    #pragma unroll
    for (int o = 16; o; o >>= 1) {
        sum += __shfl_xor_sync(0xffffffffu, sum, o);
        sq  += __shfl_xor_sync(0xffffffffu, sq,  o);
    }
    __shared__ float red0[8], red1[8];
    __shared__ float s_mean, s_rstd;
    int w = d >> 5, lane = d & 31;
    if (lane == 0) { red0[w] = sum; red1[w] = sq; }
    __syncthreads();
    if (w == 0) {
        float a = (lane < 8) ? red0[lane] : 0.f;
        float c = (lane < 8) ? red1[lane] : 0.f;
        #pragma unroll
        for (int o = 4; o; o >>= 1) {
            a += __shfl_xor_sync(0xffffffffu, a, o);
            c += __shfl_xor_sync(0xffffffffu, c, o);
        }
        if (lane == 0) {
            float mean = a * (1.0f/DD);
            float var  = c * (1.0f/DD) - mean*mean;
            s_mean = mean;
            s_rstd = rsqrtf(var + 1e-5f);
        }
    }
    __syncthreads();
    out[t*DD + d] = (v - s_mean) * s_rstd * sc[d] + bi[d];
}

// ============================================================
// host orchestration
// ============================================================
extern "C" void kernel_launch(void* const* d_in, const int* in_sizes, int n_in,
                              void* d_out, int out_size) {
    const float* x     = (const float*)d_in[0];
    const float* ln0_s = (const float*)d_in[1];
    const float* ln0_b = (const float*)d_in[2];
    const float* ln1_s = (const float*)d_in[3];
    const float* ln1_b = (const float*)d_in[4];
    const float* ln2_s = (const float*)d_in[5];
    const float* ln2_b = (const float*)d_in[6];
    const float* wq = (const float*)d_in[7];
    const float* bq = (const float*)d_in[8];
    const float* wk = (const float*)d_in[9];
    const float* bk = (const float*)d_in[10];
    const float* wv = (const float*)d_in[11];
    const float* bv = (const float*)d_in[12];
    const float* wo = (const float*)d_in[13];
    const float* bo = (const float*)d_in[14];
    const float* w1 = (const float*)d_in[15];
    const float* b1 = (const float*)d_in[16];
    const float* w2 = (const float*)d_in[17];
    const float* b2 = (const float*)d_in[18];
    float* out = (float*)d_out;

    float *px, *px2, *pqkv, *po, *pff;
    float *pwqkvT, *pbqkv, *pwoT, *pw1T, *pw2T;
    cudaGetSymbolAddress((void**)&px,    g_x);
    cudaGetSymbolAddress((void**)&px2,   g_x2);
    cudaGetSymbolAddress((void**)&pqkv,  g_qkv);
    cudaGetSymbolAddress((void**)&po,    g_o);
    cudaGetSymbolAddress((void**)&pff,   g_ff);
    cudaGetSymbolAddress((void**)&pwqkvT,g_wqkvT);
    cudaGetSymbolAddress((void**)&pbqkv, g_bqkv);
    cudaGetSymbolAddress((void**)&pwoT,  g_woT);
    cudaGetSymbolAddress((void**)&pw1T,  g_w1T);
    cudaGetSymbolAddress((void**)&pw2T,  g_w2T);

    dim3 tt(32, 8);
    // q/k/v into fused [768][256] layout
    transpose_k2<<<dim3(DD/32,  DD/32,  LL), tt>>>(wq, pwqkvT, DD, DD, QKVN, 0);
    transpose_k2<<<dim3(DD/32,  DD/32,  LL), tt>>>(wk, pwqkvT, DD, DD, QKVN, 256);
    transpose_k2<<<dim3(DD/32,  DD/32,  LL), tt>>>(wv, pwqkvT, DD, DD, QKVN, 512);
    transpose_k2<<<dim3(DD/32,  DD/32,  LL), tt>>>(wo, pwoT, DD, DD,  DD,  0);
    transpose_k2<<<dim3(FFD/32, DD/32,  LL), tt>>>(w1, pw1T, DD, FFD, FFD, 0);
    transpose_k2<<<dim3(DD/32,  FFD/32, LL), tt>>>(w2, pw2T, FFD, DD, DD,  0);
    concat_bias<<<LL, 256>>>(bq, bk, bv, pbqkv);

    dim3 g_d   (NTOK/128, DD/128);     // (64, 2)
    dim3 g_qkvg(NTOK/128, QKVN/128);   // (64, 6)
    dim3 g_ff1 (NTOK/128, FFD/128);    // (64, 4)
    dim3 g_attn(SS/128, BB*HH);        // (16, 32)

    ln_kernel<<<NTOK, 256>>>(x, px, ln0_s, ln0_b);

    for (int l = 0; l < LL; l++) {
        const float* l1s = ln1_s + l*DD; const float* l1b = ln1_b + l*DD;
        const float* l2s = ln2_s + l*DD; const float* l2b = ln2_b + l*DD;
        const float* WqkvT = pwqkvT + (size_t)l*QKVN*DD;
        const float* Bqkv  = pbqkv  + (size_t)l*QKVN;
        const float* WoT = pwoT + (size_t)l*DD*DD;  const float* Bo = bo + l*DD;
        const float* W1T = pw1T + (size_t)l*DD*FFD; const float* B1 = b1 + l*FFD;
        const float* W2T = pw2T + (size_t)l*FFD*DD; const float* B2 = b2 + l*DD;

        ln_kernel<<<NTOK, 256>>>(px, px2, l1s, l1b);
        mma_gemm<QKVN, DD, 0, false><<<g_qkvg, 256>>>(px2, WqkvT, Bqkv, nullptr, pqkv);
        attn_mma2<<<g_attn, 256>>>(pqkv, pqkv + 256, pqkv + 512, po);
        mma_gemm<DD, DD, 0, true><<<g_d, 256>>>(po, WoT, Bo, px, px);

        ln_kernel<<<NTOK, 256>>>(px, px2, l2s, l2b);
        mma_gemm<FFD, DD, 1, false><<<g_ff1, 256>>>(px2, W1T, B1, nullptr, pff);
        float* dst = (l == LL-1) ? out : px;
        mma_gemm<DD, FFD, 0, true><<<g_d, 256>>>(pff, W2T, B2, px, dst);
    }
}

// round 5
// speedup vs baseline: 3.1555x; 1.2720x over previous
#include <cuda_runtime.h>
#include <math.h>
#include <stdint.h>

// Problem constants
#define BB   4
#define SS   2048
#define DD   256
#define HH   8
#define LL   4
#define FFD  512
#define DK   32
#define NTOK (BB*SS)        // 8192
#define QKVN 768
#define SCALE 0.17677669529663687f  // 1/sqrt(32)
#define LOG2E 1.4426950408889634f

// -------- device scratch (no allocations allowed) --------
__device__ float g_x  [NTOK*DD];
__device__ float g_x2 [NTOK*DD];
__device__ float g_qkv[NTOK*QKVN];
__device__ float g_o  [NTOK*DD];
__device__ float g_ff [NTOK*FFD];
// transposed weights
__device__ float g_wqkvT[LL*QKVN*DD];   // rows 0-255: q, 256-511: k, 512-767: v
__device__ float g_bqkv [LL*QKVN];
__device__ float g_woT[LL*DD*DD];
__device__ float g_w1T[LL*DD*FFD];
__device__ float g_w2T[LL*FFD*DD];

// ============================================================
// helpers
// ============================================================
__device__ __forceinline__ uint32_t fu(float f) { return __float_as_uint(f); }

// D += A(16x8) * B(8x8), tf32 in, f32 accum
__device__ __forceinline__ void mma8(float* d, const uint32_t* a, uint32_t b0, uint32_t b1) {
    asm volatile(
        "mma.sync.aligned.m16n8k8.row.col.f32.tf32.tf32.f32 "
        "{%0,%1,%2,%3}, {%4,%5,%6,%7}, {%8,%9}, {%0,%1,%2,%3};"
        : "+f"(d[0]), "+f"(d[1]), "+f"(d[2]), "+f"(d[3])
        : "r"(a[0]), "r"(a[1]), "r"(a[2]), "r"(a[3]), "r"(b0), "r"(b1));
}
__device__ __forceinline__ uint32_t smem_u32(const void* p) {
    uint32_t a;
    asm("{ .reg .u64 t; cvta.to.shared.u64 t, %1; cvt.u32.u64 %0, t; }" : "=r"(a) : "l"(p));
    return a;
}
__device__ __forceinline__ void cpa16(uint32_t saddr, const void* g) {
    asm volatile("cp.async.ca.shared.global [%0], [%1], 16;" :: "r"(saddr), "l"(g));
}
#define CPA_COMMIT() asm volatile("cp.async.commit_group;" ::: "memory")

// swizzled smem read: row stride 32 words, float4-granule XOR swizzle
__device__ __forceinline__ float lds_sw(const float* b, int r, int col) {
    return b[r * 32 + ((((col >> 2) ^ (r & 7)) << 2) | (col & 3))];
}

// ============================================================
// Fused weight prep: all transposes [z][K][N]->[rows][K] + bias concat.
// grid (512, LL), block (32, 8)
// ============================================================
__global__ void prep_weights(
    const float* __restrict__ wq, const float* __restrict__ wk,
    const float* __restrict__ wv, const float* __restrict__ wo,
    const float* __restrict__ w1, const float* __restrict__ w2,
    const float* __restrict__ bq, const float* __restrict__ bk,
    const float* __restrict__ bv,
    float* __restrict__ qkvT, float* __restrict__ woT,
    float* __restrict__ w1T,  float* __restrict__ w2T,
    float* __restrict__ bqkv)
{
    __shared__ float t[32][33];
    const int id = blockIdx.x;
    const int z  = blockIdx.y;
    const int tx = threadIdx.x, ty = threadIdx.y;

    const float* src; float* dst;
    int K, N, layerRows, rowoff, nt, kt;
    if (id < 64)       { src = wq; dst = qkvT; K=256; N=256; layerRows=768; rowoff=0;   int l=id;     nt=l&7;  kt=l>>3; }
    else if (id < 128) { src = wk; dst = qkvT; K=256; N=256; layerRows=768; rowoff=256; int l=id-64;  nt=l&7;  kt=l>>3; }
    else if (id < 192) { src = wv; dst = qkvT; K=256; N=256; layerRows=768; rowoff=512; int l=id-128; nt=l&7;  kt=l>>3; }
    else if (id < 256) { src = wo; dst = woT;  K=256; N=256; layerRows=256; rowoff=0;   int l=id-192; nt=l&7;  kt=l>>3; }
    else if (id < 384) { src = w1; dst = w1T;  K=256; N=512; layerRows=512; rowoff=0;   int l=id-256; nt=l&15; kt=l>>4; }
    else               { src = w2; dst = w2T;  K=512; N=256; layerRows=256; rowoff=0;   int l=id-384; nt=l&7;  kt=l>>3; }

    src += (size_t)z * K * N;
    #pragma unroll
    for (int j = ty; j < 32; j += 8)
        t[j][tx] = src[(size_t)(kt*32 + j) * N + nt*32 + tx];
    __syncthreads();
    #pragma unroll
    for (int j = ty; j < 32; j += 8)
        dst[((size_t)z * layerRows + rowoff + nt*32 + j) * K + kt*32 + tx] = t[tx][j];

    if (id == 0) {
        int d = ty * 32 + tx;   // 0..255
        bqkv[z*QKVN + d]       = bq[z*DD + d];
        bqkv[z*QKVN + 256 + d] = bk[z*DD + d];
        bqkv[z*QKVN + 512 + d] = bv[z*DD + d];
    }
}

// ============================================================
// tf32 mma GEMM, cp.async double-buffered.
// C[M,N] = act(A[M,K] @ Wt^T + bias) (+res). Wt is [N][K].
// CTA tile 128x128, BK=32, 8 warps (warp tile 64x32).
// dynamic smem: 2 stages x (A 16KB + B 16KB) = 64KB
// ============================================================
template<int N, int K, int ACT, bool RES>
__global__ void __launch_bounds__(256) mma_gemm(
    const float* __restrict__ A, const float* __restrict__ Wt,
    const float* __restrict__ bias, const float* __restrict__ res,
    float* __restrict__ C)
{
    extern __shared__ float smp[];
    const int tid = threadIdx.x;
    const int wid = tid >> 5, lane = tid & 31;
    const int g = lane >> 2, c = lane & 3;
    const int m0 = blockIdx.x * 128, n0 = blockIdx.y * 128;
    const int wm = (wid & 1) * 64;
    const int wn = (wid >> 1) * 32;
    const uint32_t sbase = smem_u32(smp);

    constexpr int NC = K / 32;
    float acc[4][4][4] = {};

    // stage chunk 0 into buffer 0
    {
        #pragma unroll
        for (int i = 0; i < 4; i++) {
            int idx = tid + 256 * i;
            int r = idx >> 3, c4 = idx & 7;
            uint32_t sw = (uint32_t)((c4 ^ (r & 7)) << 4);
            cpa16(sbase + r * 128 + sw,         A  + (size_t)(m0 + r) * K + c4 * 4);
            cpa16(sbase + 16384 + r * 128 + sw, Wt + (size_t)(n0 + r) * K + c4 * 4);
        }
        CPA_COMMIT();
    }

    for (int ch = 0; ch < NC; ch++) {
        if (ch + 1 < NC) {
            const int kc = (ch + 1) * 32;
            const uint32_t b0 = sbase + ((ch + 1) & 1) * 32768;
            #pragma unroll
            for (int i = 0; i < 4; i++) {
                int idx = tid + 256 * i;
                int r = idx >> 3, c4 = idx & 7;
                uint32_t sw = (uint32_t)((c4 ^ (r & 7)) << 4);
                cpa16(b0 + r * 128 + sw,         A  + (size_t)(m0 + r) * K + kc + c4 * 4);
                cpa16(b0 + 16384 + r * 128 + sw, Wt + (size_t)(n0 + r) * K + kc + c4 * 4);
            }
            CPA_COMMIT();
            asm volatile("cp.async.wait_group 1;" ::: "memory");
        } else {
            asm volatile("cp.async.wait_group 0;" ::: "memory");
        }
        __syncthreads();

        const float* Ab = smp + (ch & 1) * 8192;
        const float* Bb = Ab + 4096;

        #pragma unroll
        for (int k8 = 0; k8 < 4; k8++) {
            uint32_t a[4][4];
            #pragma unroll
            for (int mf = 0; mf < 4; mf++) {
                int r0 = wm + mf * 16 + g;
                a[mf][0] = fu(lds_sw(Ab, r0,     k8 * 8 + c    ));
                a[mf][1] = fu(lds_sw(Ab, r0 + 8, k8 * 8 + c    ));
                a[mf][2] = fu(lds_sw(Ab, r0,     k8 * 8 + c + 4));
                a[mf][3] = fu(lds_sw(Ab, r0 + 8, k8 * 8 + c + 4));
            }
            #pragma unroll
            for (int nf = 0; nf < 4; nf++) {
                int rn = wn + nf * 8 + g;
                uint32_t b0 = fu(lds_sw(Bb, rn, k8 * 8 + c    ));
                uint32_t b1 = fu(lds_sw(Bb, rn, k8 * 8 + c + 4));
                #pragma unroll
                for (int mf = 0; mf < 4; mf++)
                    mma8(acc[mf][nf], a[mf], b0, b1);
            }
        }
        __syncthreads();
    }

    // epilogue
    #pragma unroll
    for (int nf = 0; nf < 4; nf++) {
        int col = n0 + wn + nf * 8 + 2 * c;
        float2 bb = *(const float2*)(bias + col);
        #pragma unroll
        for (int mf = 0; mf < 4; mf++) {
            #pragma unroll
            for (int half = 0; half < 2; half++) {
                int row = m0 + wm + mf * 16 + g + half * 8;
                float vx = acc[mf][nf][half * 2 + 0] + bb.x;
                float vy = acc[mf][nf][half * 2 + 1] + bb.y;
                if (ACT == 1) { vx = fmaxf(vx, 0.f); vy = fmaxf(vy, 0.f); }
                if (RES) {
                    float2 r2 = *(const float2*)(res + (size_t)row * N + col);
                    vx += r2.x; vy += r2.y;
                }
                float2 o2 = {vx, vy};
                *(float2*)(C + (size_t)row * N + col) = o2;
            }
        }
    }
}

// ============================================================
// Flash attention v2 (tf32 mma, Q in regs, P via shuffles,
// cp.async double-buffered K/V). 256 thr, Q tile 128, KV tile 64.
// Q/K/V rows have stride QKVN (fused qkv buffer).
// ============================================================
__global__ void __launch_bounds__(256) attn_mma2(
    const float* __restrict__ Qg, const float* __restrict__ Kg,
    const float* __restrict__ Vg, float* __restrict__ Og)
{
    __shared__ float Ks[2][64][36];
    __shared__ float Vs[2][64][36];

    const int tid = threadIdx.x;
    const int wid = tid >> 5, lane = tid & 31;
    const int g = lane >> 2, c = lane & 3;
    const int bh = blockIdx.y;
    const int b = bh >> 3, h = bh & 7;
    const int s0 = blockIdx.x * 128;
    const int wq0 = wid * 16;
    const float SC2 = SCALE * LOG2E;

    const uint32_t sKs = smem_u32(&Ks[0][0][0]);
    const uint32_t sVs = smem_u32(&Vs[0][0][0]);

    uint32_t qa[4][4];
    {
        const float* qb = Qg + (size_t)(b * SS + s0 + wq0) * QKVN + h * DK;
        #pragma unroll
        for (int k8 = 0; k8 < 4; k8++) {
            qa[k8][0] = fu(qb[(size_t)g       * QKVN + k8 * 8 + c    ] * SC2);
            qa[k8][1] = fu(qb[(size_t)(g + 8) * QKVN + k8 * 8 + c    ] * SC2);
            qa[k8][2] = fu(qb[(size_t)g       * QKVN + k8 * 8 + c + 4] * SC2);
            qa[k8][3] = fu(qb[(size_t)(g + 8) * QKVN + k8 * 8 + c + 4] * SC2);
        }
    }

    float m0v = -INFINITY, m1v = -INFINITY;
    float l0 = 0.f, l1 = 0.f;
    float o[4][4] = {};

    {
        #pragma unroll
        for (int i = tid; i < 512; i += 256) {
            int r = i >> 3, j = i & 7;
            const size_t gbase = (size_t)(b * SS + r) * QKVN + h * DK + j * 4;
            uint32_t soff = (uint32_t)((r * 36 + j * 4) * 4);
            cpa16(sKs + soff, Kg + gbase);
            cpa16(sVs + soff, Vg + gbase);
        }
        CPA_COMMIT();
    }

    for (int t = 0; t < SS / 64; t++) {
        const int bf = t & 1;
        asm volatile("cp.async.wait_group 0;" ::: "memory");
        __syncthreads();

        if (t + 1 < SS / 64) {
            const int kv0 = (t + 1) * 64;
            const int nbf = bf ^ 1;
            #pragma unroll
            for (int i = tid; i < 512; i += 256) {
                int r = i >> 3, j = i & 7;
                const size_t gbase = (size_t)(b * SS + kv0 + r) * QKVN + h * DK + j * 4;
                uint32_t soff = (uint32_t)(((nbf * 64 + r) * 36 + j * 4) * 4);
                cpa16(sKs + soff, Kg + gbase);
                cpa16(sVs + soff, Vg + gbase);
            }
            CPA_COMMIT();
        }

        float s[8][4] = {};
        #pragma unroll
        for (int k8 = 0; k8 < 4; k8++) {
            #pragma unroll
            for (int nf = 0; nf < 8; nf++) {
                uint32_t b0 = fu(Ks[bf][nf * 8 + g][k8 * 8 + c    ]);
                uint32_t b1 = fu(Ks[bf][nf * 8 + g][k8 * 8 + c + 4]);
                mma8(s[nf], qa[k8], b0, b1);
            }
        }

        float mt0 = -INFINITY, mt1 = -INFINITY;
        #pragma unroll
        for (int nf = 0; nf < 8; nf++) {
            mt0 = fmaxf(mt0, fmaxf(s[nf][0], s[nf][1]));
            mt1 = fmaxf(mt1, fmaxf(s[nf][2], s[nf][3]));
        }
        #pragma unroll
        for (int off = 1; off <= 2; off <<= 1) {
            mt0 = fmaxf(mt0, __shfl_xor_sync(0xffffffffu, mt0, off));
            mt1 = fmaxf(mt1, __shfl_xor_sync(0xffffffffu, mt1, off));
        }
        float mn0 = fmaxf(m0v, mt0);
        float mn1 = fmaxf(m1v, mt1);
        float al0 = exp2f(m0v - mn0);
        float al1 = exp2f(m1v - mn1);
        m0v = mn0; m1v = mn1;

        float rs0 = 0.f, rs1 = 0.f;
        #pragma unroll
        for (int nf = 0; nf < 8; nf++) {
            s[nf][0] = exp2f(s[nf][0] - mn0);
            s[nf][1] = exp2f(s[nf][1] - mn0);
            s[nf][2] = exp2f(s[nf][2] - mn1);
            s[nf][3] = exp2f(s[nf][3] - mn1);
            rs0 += s[nf][0] + s[nf][1];
            rs1 += s[nf][2] + s[nf][3];
        }
        #pragma unroll
        for (int off = 1; off <= 2; off <<= 1) {
            rs0 += __shfl_xor_sync(0xffffffffu, rs0, off);
            rs1 += __shfl_xor_sync(0xffffffffu, rs1, off);
        }
        l0 = l0 * al0 + rs0;
        l1 = l1 * al1 + rs1;
        #pragma unroll
        for (int nf = 0; nf < 4; nf++) {
            o[nf][0] *= al0; o[nf][1] *= al0;
            o[nf][2] *= al1; o[nf][3] *= al1;
        }

        const int srcA = (lane & ~3) | (c >> 1);
        const int srcB = srcA + 2;
        const bool odd = (c & 1);
        #pragma unroll
        for (int k8 = 0; k8 < 8; k8++) {
            float x0 = __shfl_sync(0xffffffffu, s[k8][0], srcA);
            float x1 = __shfl_sync(0xffffffffu, s[k8][1], srcA);
            float y0 = __shfl_sync(0xffffffffu, s[k8][0], srcB);
            float y1 = __shfl_sync(0xffffffffu, s[k8][1], srcB);
            float z0 = __shfl_sync(0xffffffffu, s[k8][2], srcA);
            float z1 = __shfl_sync(0xffffffffu, s[k8][3], srcA);
            float w0 = __shfl_sync(0xffffffffu, s[k8][2], srcB);
            float w1 = __shfl_sync(0xffffffffu, s[k8][3], srcB);
            uint32_t a[4];
            a[0] = fu(odd ? x1 : x0);
            a[1] = fu(odd ? z1 : z0);
            a[2] = fu(odd ? y1 : y0);
            a[3] = fu(odd ? w1 : w0);
            #pragma unroll
            for (int nf = 0; nf < 4; nf++) {
                uint32_t b0 = fu(Vs[bf][k8 * 8 + c    ][nf * 8 + g]);
                uint32_t b1 = fu(Vs[bf][k8 * 8 + c + 4][nf * 8 + g]);
                mma8(o[nf], a, b0, b1);
            }
        }
    }

    float inv0 = 1.f / l0;
    float inv1 = 1.f / l1;
    const int row0 = b * SS + s0 + wq0 + g;
    #pragma unroll
    for (int nf = 0; nf < 4; nf++) {
        int col = h * DK + nf * 8 + 2 * c;
        float2 v0 = {o[nf][0] * inv0, o[nf][1] * inv0};
        float2 v1 = {o[nf][2] * inv1, o[nf][3] * inv1};
        *(float2*)(Og + (size_t)row0 * DD + col)       = v0;
        *(float2*)(Og + (size_t)(row0 + 8) * DD + col) = v1;
    }
}

// ============================================================
// LayerNorm: one block per token, 256 threads (= D)
// ============================================================
__global__ void ln_kernel(const float* __restrict__ in, float* __restrict__ out,
                          const float* __restrict__ sc, const float* __restrict__ bi) {
    int t = blockIdx.x;
    int d = threadIdx.x;
    float v = in[t*DD + d];
    float sum = v, sq = v*v;
    #pragma unroll
    for (int o = 16; o; o >>= 1) {
        sum += __shfl_xor_sync(0xffffffffu, sum, o);
        sq  += __shfl_xor_sync(0xffffffffu, sq,  o);
    }
    __shared__ float red0[8], red1[8];
    __shared__ float s_mean, s_rstd;
    int w = d >> 5, lane = d & 31;
    if (lane == 0) { red0[w] = sum; red1[w] = sq; }
    __syncthreads();
    if (w == 0) {
        float a = (lane < 8) ? red0[lane] : 0.f;
        float c = (lane < 8) ? red1[lane] : 0.f;
        #pragma unroll
        for (int o = 4; o; o >>= 1) {
            a += __shfl_xor_sync(0xffffffffu, a, o);
            c += __shfl_xor_sync(0xffffffffu, c, o);
        }
        if (lane == 0) {
            float mean = a * (1.0f/DD);
            float var  = c * (1.0f/DD) - mean*mean;
            s_mean = mean;
            s_rstd = rsqrtf(var + 1e-5f);
        }
    }
    __syncthreads();
    out[t*DD + d] = (v - s_mean) * s_rstd * sc[d] + bi[d];
}

// ============================================================
// host orchestration
// ============================================================
extern "C" void kernel_launch(void* const* d_in, const int* in_sizes, int n_in,
                              void* d_out, int out_size) {
    const float* x     = (const float*)d_in[0];
    const float* ln0_s = (const float*)d_in[1];
    const float* ln0_b = (const float*)d_in[2];
    const float* ln1_s = (const float*)d_in[3];
    const float* ln1_b = (const float*)d_in[4];
    const float* ln2_s = (const float*)d_in[5];
    const float* ln2_b = (const float*)d_in[6];
    const float* wq = (const float*)d_in[7];
    const float* bq = (const float*)d_in[8];
    const float* wk = (const float*)d_in[9];
    const float* bk = (const float*)d_in[10];
    const float* wv = (const float*)d_in[11];
    const float* bv = (const float*)d_in[12];
    const float* wo = (const float*)d_in[13];
    const float* bo = (const float*)d_in[14];
    const float* w1 = (const float*)d_in[15];
    const float* b1 = (const float*)d_in[16];
    const float* w2 = (const float*)d_in[17];
    const float* b2 = (const float*)d_in[18];
    float* out = (float*)d_out;

    float *px, *px2, *pqkv, *po, *pff;
    float *pwqkvT, *pbqkv, *pwoT, *pw1T, *pw2T;
    cudaGetSymbolAddress((void**)&px,    g_x);
    cudaGetSymbolAddress((void**)&px2,   g_x2);
    cudaGetSymbolAddress((void**)&pqkv,  g_qkv);
    cudaGetSymbolAddress((void**)&po,    g_o);
    cudaGetSymbolAddress((void**)&pff,   g_ff);
    cudaGetSymbolAddress((void**)&pwqkvT,g_wqkvT);
    cudaGetSymbolAddress((void**)&pbqkv, g_bqkv);
    cudaGetSymbolAddress((void**)&pwoT,  g_woT);
    cudaGetSymbolAddress((void**)&pw1T,  g_w1T);
    cudaGetSymbolAddress((void**)&pw2T,  g_w2T);

    // dynamic smem opt-in (64KB) for all gemm instantiations
    static const int SMEM_BYTES = 65536;
    cudaFuncSetAttribute(mma_gemm<QKVN, DD, 0, false>, cudaFuncAttributeMaxDynamicSharedMemorySize, SMEM_BYTES);
    cudaFuncSetAttribute(mma_gemm<DD,   DD, 0, true >, cudaFuncAttributeMaxDynamicSharedMemorySize, SMEM_BYTES);
    cudaFuncSetAttribute(mma_gemm<FFD,  DD, 1, false>, cudaFuncAttributeMaxDynamicSharedMemorySize, SMEM_BYTES);
    cudaFuncSetAttribute(mma_gemm<DD,  FFD, 0, true >, cudaFuncAttributeMaxDynamicSharedMemorySize, SMEM_BYTES);

    prep_weights<<<dim3(512, LL), dim3(32, 8)>>>(wq, wk, wv, wo, w1, w2, bq, bk, bv,
                                                 pwqkvT, pwoT, pw1T, pw2T, pbqkv);

    dim3 g_d   (NTOK/128, DD/128);     // (64, 2)
    dim3 g_qkvg(NTOK/128, QKVN/128);   // (64, 6)
    dim3 g_ff1 (NTOK/128, FFD/128);    // (64, 4)
    dim3 g_attn(SS/128, BB*HH);        // (16, 32)

    ln_kernel<<<NTOK, 256>>>(x, px, ln0_s, ln0_b);

    for (int l = 0; l < LL; l++) {
        const float* l1s = ln1_s + l*DD; const float* l1b = ln1_b + l*DD;
        const float* l2s = ln2_s + l*DD; const float* l2b = ln2_b + l*DD;
        const float* WqkvT = pwqkvT + (size_t)l*QKVN*DD;
        const float* Bqkv  = pbqkv  + (size_t)l*QKVN;
        const float* WoT = pwoT + (size_t)l*DD*DD;  const float* Bo = bo + l*DD;
        const float* W1T = pw1T + (size_t)l*DD*FFD; const float* B1 = b1 + l*FFD;
        const float* W2T = pw2T + (size_t)l*FFD*DD; const float* B2 = b2 + l*DD;

        ln_kernel<<<NTOK, 256>>>(px, px2, l1s, l1b);
        mma_gemm<QKVN, DD, 0, false><<<g_qkvg, 256, SMEM_BYTES>>>(px2, WqkvT, Bqkv, nullptr, pqkv);
        attn_mma2<<<g_attn, 256>>>(pqkv, pqkv + 256, pqkv + 512, po);
        mma_gemm<DD, DD, 0, true><<<g_d, 256, SMEM_BYTES>>>(po, WoT, Bo, px, px);

        ln_kernel<<<NTOK, 256>>>(px, px2, l2s, l2b);
        mma_gemm<FFD, DD, 1, false><<<g_ff1, 256, SMEM_BYTES>>>(px2, W1T, B1, nullptr, pff);
        float* dst = (l == LL-1) ? out : px;
        mma_gemm<DD, FFD, 0, true><<<g_d, 256, SMEM_BYTES>>>(pff, W2T, B2, px, dst);
    }
}